// round 11
// baseline (speedup 1.0000x reference)
#include <cuda_runtime.h>
#include <cstdint>

#define NTOK 64
#define DIM  128
#define B1N  2048
#define B2N  8192
#define QSCALE 0.17677669529663687f
#define X_ELEMS 16777216   // B1N*NTOK*DIM

// g_Q[b][8192] tiled: tile=(n>>3)*16+(k>>3), pos=(n&7)*8+2*(k&3)+((k&4)>>2)
__device__ float g_Q[(size_t)B1N * 8192];

__device__ __forceinline__ float to_tf32(float x) {
    float r; asm("cvt.rna.tf32.f32 %0, %1;" : "=f"(r) : "f"(x)); return r;
}
__device__ __forceinline__ void mma_tf32(float c[4],
    uint32_t a0, uint32_t a1, uint32_t a2, uint32_t a3,
    uint32_t b0, uint32_t b1)
{
    asm volatile(
        "mma.sync.aligned.m16n8k8.row.col.f32.tf32.tf32.f32 "
        "{%0,%1,%2,%3},{%4,%5,%6,%7},{%8,%9},{%0,%1,%2,%3};"
        : "+f"(c[0]), "+f"(c[1]), "+f"(c[2]), "+f"(c[3])
        : "r"(a0), "r"(a1), "r"(a2), "r"(a3), "r"(b0), "r"(b1));
}

__device__ __forceinline__ int tiled_nk(int n, int k) {   // Q/K/W/A layout
    return ((n >> 3) * 16 + (k >> 3)) * 64 + (n & 7) * 8 + 2 * (k & 3) + ((k & 4) >> 2);
}
__device__ __forceinline__ int tiled_v(int m, int d) {    // V layout
    return ((m >> 3) * 16 + (d >> 3)) * 64 + (d & 7) * 8 + 2 * (m & 3) + ((m & 4) >> 2);
}

// ---------------------------------------------------------------------------
// Kernel A: Q = tf32( scale * (x1 @ W1^T + b1) )  [unchanged - committed win]
// ---------------------------------------------------------------------------
#define QK_SMEM_FLOATS (8448 + 4608)

__global__ void __launch_bounds__(256) q_kernel(
    const float* __restrict__ x1, const float* __restrict__ w1,
    const float* __restrict__ bias1)
{
    extern __shared__ float sm[];
    float* a_s = sm;
    float* w_s = sm + 8448;

    const int t = threadIdx.x, b = blockIdx.x;
    const int lane = t & 31, wid = t >> 5;
    const int m_base = (wid & 3) * 16;
    const int n_base = (wid >> 2) * 64;
    const int r0 = lane >> 2, cth = lane & 3;

    const float* xb = x1 + (size_t)b * (NTOK * DIM);
    for (int idx = t; idx < NTOK * DIM; idx += 256) {
        int m = idx >> 7, k = idx & 127;
        a_s[m * 132 + k] = to_tf32(xb[idx]);
    }

    float c[8][4];
#pragma unroll
    for (int nt = 0; nt < 8; nt++)
#pragma unroll
        for (int j = 0; j < 4; j++) c[nt][j] = 0.f;

    for (int kc = 0; kc < 4; kc++) {
        __syncthreads();
        for (int idx = t; idx < 4096; idx += 256) {
            int j = idx >> 5, kk = idx & 31;
            w_s[j * 36 + kk] = to_tf32(w1[j * DIM + kc * 32 + kk]);
        }
        __syncthreads();
#pragma unroll
        for (int ks = 0; ks < 4; ks++) {
            const int col = kc * 32 + ks * 8 + cth;
            const uint32_t a0 = __float_as_uint(a_s[(m_base + r0) * 132 + col]);
            const uint32_t a1 = __float_as_uint(a_s[(m_base + r0 + 8) * 132 + col]);
            const uint32_t a2 = __float_as_uint(a_s[(m_base + r0) * 132 + col + 4]);
            const uint32_t a3 = __float_as_uint(a_s[(m_base + r0 + 8) * 132 + col + 4]);
#pragma unroll
            for (int nt = 0; nt < 8; nt++) {
                const int j = n_base + nt * 8 + r0;
                const uint32_t b0 = __float_as_uint(w_s[j * 36 + ks * 8 + cth]);
                const uint32_t b1 = __float_as_uint(w_s[j * 36 + ks * 8 + 4 + cth]);
                mma_tf32(c[nt], a0, a1, a2, a3, b0, b1);
            }
        }
    }

    float* qb = g_Q + (size_t)b * 8192;
    const int row0 = m_base + r0;
#pragma unroll
    for (int nt = 0; nt < 8; nt++) {
        const int col0 = n_base + nt * 8 + 2 * cth;
        const float2 bv = *(const float2*)(bias1 + col0);
        qb[tiled_nk(row0,     col0    )] = to_tf32((c[nt][0] + bv.x) * QSCALE);
        qb[tiled_nk(row0,     col0 + 1)] = to_tf32((c[nt][1] + bv.y) * QSCALE);
        qb[tiled_nk(row0 + 8, col0    )] = to_tf32((c[nt][2] + bv.x) * QSCALE);
        qb[tiled_nk(row0 + 8, col0 + 1)] = to_tf32((c[nt][3] + bv.y) * QSCALE);
    }
}

// ---------------------------------------------------------------------------
// FUSED kernel: per b1 CTA, for r=0..3:
//   stage x2[b2] tiled -> kv mma (W2 resident) -> K|V tiled in smem ->
//   QK^T + bias + softmax + attn write + PV  (all tf32 mma)
// then proj via tf32 mma (pw staged into the dead W2 area).
// 512 thr, 16 warps. kv roles: m_base=(w&3)*16, n_base=(w>>2)*64.
//                    attn roles: h=w>>2, R0=(w&3)*16.
// ---------------------------------------------------------------------------
#define SM_W   0        // 32768 : W2 tiled (tail: pw tiled in [0:16384))
#define SM_R   32768    // 16384 : x2 tiled [0:8192) -> K tiled [0:8192) | V [8192:16384)
#define SM_RELB 49152   // uint8[4096] = 1024 floats
#define SM_TABF (SM_RELB + 1024)          // 50176 : 900
#define FUSED_SMEM_FLOATS (SM_TABF + 900) // 51076 floats = 204304 B

__global__ void __launch_bounds__(512, 1) fused_kernel(
    const float* __restrict__ x2, const float* __restrict__ w2,
    const float* __restrict__ bias2,
    const float* __restrict__ pw, const float* __restrict__ pb,
    const float* __restrict__ rpb, const int* __restrict__ rel,
    float* __restrict__ out)
{
    extern __shared__ float sm[];
    float*   w_s   = sm + SM_W;
    float*   reg   = sm + SM_R;
    uint8_t* rel_s = (uint8_t*)(sm + SM_RELB);
    float*   tab_s = sm + SM_TABF;

    const int t    = threadIdx.x;
    const int bdst = blockIdx.x;
    const int lane = t & 31, wid = t >> 5;
    // kv roles
    const int m_base = (wid & 3) * 16;
    const int n_base = (wid >> 2) * 64;
    // attn roles
    const int h  = wid >> 2;
    const int R0 = (wid & 3) * 16;
    const int r0 = lane >> 2, cth = lane & 3;
    const int n_lo = R0 + r0, n_hi = n_lo + 8;
    const int ldoff = r0 * 8 + 2 * cth;

    // ---- one-time staging: W2 tiled, rel (uint8), tab ----
    for (int idx = t; idx < 8192; idx += 512) {
        const int j = idx >> 5, k4 = (idx & 31) * 4;
        const float4 w = *(const float4*)(w2 + j * DIM + k4);
        w_s[tiled_nk(j, k4 + 0)] = to_tf32(w.x);
        w_s[tiled_nk(j, k4 + 1)] = to_tf32(w.y);
        w_s[tiled_nk(j, k4 + 2)] = to_tf32(w.z);
        w_s[tiled_nk(j, k4 + 3)] = to_tf32(w.w);
    }
    for (int idx = t; idx < 4096; idx += 512)
        rel_s[idx] = (uint8_t)rel[idx];
    for (int idx = t; idx < 225 * 4; idx += 512)
        tab_s[idx] = rpb[idx];

    float oacc[4][4];
#pragma unroll
    for (int nt = 0; nt < 4; nt++)
#pragma unroll
        for (int j = 0; j < 4; j++) oacc[nt][j] = 0.f;

    for (int r = 0; r < 4; r++) {
        const int b2 = bdst * 4 + r;

        __syncthreads();   // prev attn readers of reg done (r=0: setup stores ordered)

        // ---- stage x2[b2] tiled into reg[0:8192) ----
        const float4* xb = (const float4*)(x2 + (size_t)b2 * 8192);
#pragma unroll
        for (int i = 0; i < 4; i++) {
            const int idx = t + i * 512;
            const int m = idx >> 5, k4 = (idx & 31) * 4;
            const float4 v = xb[idx];
            reg[tiled_nk(m, k4 + 0)] = to_tf32(v.x);
            reg[tiled_nk(m, k4 + 1)] = to_tf32(v.y);
            reg[tiled_nk(m, k4 + 2)] = to_tf32(v.z);
            reg[tiled_nk(m, k4 + 3)] = to_tf32(v.w);
        }
        __syncthreads();

        // ---- kv mma: c = x2 @ W2^T  (per warp 16x64 of 64x256) ----
        float c[8][4];
#pragma unroll
        for (int nt = 0; nt < 8; nt++)
#pragma unroll
            for (int j = 0; j < 4; j++) c[nt][j] = 0.f;

#pragma unroll
        for (int kt = 0; kt < 16; kt++) {
            const float2 alo = *(const float2*)&reg[(((m_base >> 3)    ) * 16 + kt) * 64 + ldoff];
            const float2 ahi = *(const float2*)&reg[(((m_base >> 3) + 1) * 16 + kt) * 64 + ldoff];
            const uint32_t a0 = __float_as_uint(alo.x);
            const uint32_t a1 = __float_as_uint(ahi.x);
            const uint32_t a2 = __float_as_uint(alo.y);
            const uint32_t a3 = __float_as_uint(ahi.y);
#pragma unroll
            for (int nt = 0; nt < 8; nt++) {
                const float2 bp = *(const float2*)&w_s[(((n_base >> 3) + nt) * 16 + kt) * 64 + ldoff];
                mma_tf32(c[nt], a0, a1, a2, a3,
                         __float_as_uint(bp.x), __float_as_uint(bp.y));
            }
        }
        __syncthreads();   // all x2 reads done before K|V overwrite

        // ---- epilogue: +bias, tf32-round, STS K|V tiled into reg ----
        const int row0 = m_base + r0;
#pragma unroll
        for (int nt = 0; nt < 8; nt++) {
            const int col0 = n_base + nt * 8 + 2 * cth;
            const float2 bv = *(const float2*)(bias2 + col0);
            const float v00 = to_tf32(c[nt][0] + bv.x);
            const float v01 = to_tf32(c[nt][1] + bv.y);
            const float v10 = to_tf32(c[nt][2] + bv.x);
            const float v11 = to_tf32(c[nt][3] + bv.y);
            if (col0 < DIM) {
                reg[tiled_nk(row0,     col0    )] = v00;
                reg[tiled_nk(row0,     col0 + 1)] = v01;
                reg[tiled_nk(row0 + 8, col0    )] = v10;
                reg[tiled_nk(row0 + 8, col0 + 1)] = v11;
            } else {
                const int d0 = col0 - DIM;
                reg[8192 + tiled_v(row0,     d0    )] = v00;
                reg[8192 + tiled_v(row0,     d0 + 1)] = v01;
                reg[8192 + tiled_v(row0 + 8, d0    )] = v10;
                reg[8192 + tiled_v(row0 + 8, d0 + 1)] = v11;
            }
        }
        __syncthreads();   // K|V visible

        float* k_s = reg;
        float* v_s = reg + 8192;

        // ---- Q A-frags direct from gmem (tiled, L2-resident) ----
        const int qb = b2 & (B1N - 1);
        const float* qg = g_Q + (size_t)qb * 8192;
        float2 qalo[4], qahi[4];
#pragma unroll
        for (int ks = 0; ks < 4; ks++) {
            const int kt = h * 4 + ks;
            qalo[ks] = *(const float2*)&qg[(((R0 >> 3)    ) * 16 + kt) * 64 + ldoff];
            qahi[ks] = *(const float2*)&qg[(((R0 >> 3) + 1) * 16 + kt) * 64 + ldoff];
        }

        // ---- S = Q K^T ----
#pragma unroll
        for (int nt = 0; nt < 8; nt++)
#pragma unroll
            for (int j = 0; j < 4; j++) c[nt][j] = 0.f;

#pragma unroll
        for (int ks = 0; ks < 4; ks++) {
            const int kt = h * 4 + ks;
            const uint32_t a0 = __float_as_uint(qalo[ks].x);
            const uint32_t a1 = __float_as_uint(qahi[ks].x);
            const uint32_t a2 = __float_as_uint(qalo[ks].y);
            const uint32_t a3 = __float_as_uint(qahi[ks].y);
#pragma unroll
            for (int nt = 0; nt < 8; nt++) {
                const float2 bp = *(const float2*)&k_s[(nt * 16 + kt) * 64 + ldoff];
                mma_tf32(c[nt], a0, a1, a2, a3,
                         __float_as_uint(bp.x), __float_as_uint(bp.y));
            }
        }

        // ---- + relative position bias (uint8 indices) ----
#pragma unroll
        for (int nt = 0; nt < 8; nt++) {
            const int m = nt * 8 + 2 * cth;
            const uint16_t rlo = *(const uint16_t*)&rel_s[n_lo * 64 + m];
            const uint16_t rhi = *(const uint16_t*)&rel_s[n_hi * 64 + m];
            c[nt][0] += tab_s[(rlo & 0xff) * 4 + h];
            c[nt][1] += tab_s[(rlo >> 8) * 4 + h];
            c[nt][2] += tab_s[(rhi & 0xff) * 4 + h];
            c[nt][3] += tab_s[(rhi >> 8) * 4 + h];
        }

        // ---- softmax ----
        float mx0 = -1e30f, mx1 = -1e30f;
#pragma unroll
        for (int nt = 0; nt < 8; nt++) {
            mx0 = fmaxf(mx0, fmaxf(c[nt][0], c[nt][1]));
            mx1 = fmaxf(mx1, fmaxf(c[nt][2], c[nt][3]));
        }
        mx0 = fmaxf(mx0, __shfl_xor_sync(0xffffffffu, mx0, 1));
        mx0 = fmaxf(mx0, __shfl_xor_sync(0xffffffffu, mx0, 2));
        mx1 = fmaxf(mx1, __shfl_xor_sync(0xffffffffu, mx1, 1));
        mx1 = fmaxf(mx1, __shfl_xor_sync(0xffffffffu, mx1, 2));

        float s0 = 0.f, s1 = 0.f;
#pragma unroll
        for (int nt = 0; nt < 8; nt++) {
            c[nt][0] = __expf(c[nt][0] - mx0); s0 += c[nt][0];
            c[nt][1] = __expf(c[nt][1] - mx0); s0 += c[nt][1];
            c[nt][2] = __expf(c[nt][2] - mx1); s1 += c[nt][2];
            c[nt][3] = __expf(c[nt][3] - mx1); s1 += c[nt][3];
        }
        s0 += __shfl_xor_sync(0xffffffffu, s0, 1);
        s0 += __shfl_xor_sync(0xffffffffu, s0, 2);
        s1 += __shfl_xor_sync(0xffffffffu, s1, 1);
        s1 += __shfl_xor_sync(0xffffffffu, s1, 2);
        const float inv0 = 1.f / s0, inv1 = 1.f / s1;
#pragma unroll
        for (int nt = 0; nt < 8; nt++) {
            c[nt][0] *= inv0; c[nt][1] *= inv0;
            c[nt][2] *= inv1; c[nt][3] *= inv1;
        }

        // ---- write attn probs ----
        float* ao = out + (size_t)X_ELEMS + (size_t)b2 * 16384 + h * 4096;
#pragma unroll
        for (int nt = 0; nt < 8; nt++) {
            const int m = nt * 8 + 2 * cth;
            *(float2*)&ao[n_lo * 64 + m] = make_float2(c[nt][0], c[nt][1]);
            *(float2*)&ao[n_hi * 64 + m] = make_float2(c[nt][2], c[nt][3]);
        }

        // ---- round P, C-frag -> A-frag shuffles, PV mma ----
#pragma unroll
        for (int nt = 0; nt < 8; nt++)
#pragma unroll
            for (int j = 0; j < 4; j++) c[nt][j] = to_tf32(c[nt][j]);

        const int src0 = (lane & 28) + (cth >> 1);
        const int src1 = src0 + 2;
        const bool odd = (cth & 1);
#pragma unroll
        for (int ks = 0; ks < 8; ks++) {
            const float e0 = __shfl_sync(0xffffffffu, c[ks][0], src0);
            const float o0 = __shfl_sync(0xffffffffu, c[ks][1], src0);
            const float e2 = __shfl_sync(0xffffffffu, c[ks][0], src1);
            const float o2 = __shfl_sync(0xffffffffu, c[ks][1], src1);
            const float e1 = __shfl_sync(0xffffffffu, c[ks][2], src0);
            const float o1 = __shfl_sync(0xffffffffu, c[ks][3], src0);
            const float e3 = __shfl_sync(0xffffffffu, c[ks][2], src1);
            const float o3 = __shfl_sync(0xffffffffu, c[ks][3], src1);
            const uint32_t pa0 = __float_as_uint(odd ? o0 : e0);
            const uint32_t pa1 = __float_as_uint(odd ? o1 : e1);
            const uint32_t pa2 = __float_as_uint(odd ? o2 : e2);
            const uint32_t pa3 = __float_as_uint(odd ? o3 : e3);
#pragma unroll
            for (int nt = 0; nt < 4; nt++) {
                const float2 bp = *(const float2*)&v_s[(ks * 16 + h * 4 + nt) * 64 + ldoff];
                mma_tf32(oacc[nt], pa0, pa1, pa2, pa3,
                         __float_as_uint(bp.x), __float_as_uint(bp.y));
            }
        }
    } // r

    // ---- tail: O tiled -> reg, pw tiled -> w_s, proj via tf32 mma ----
    __syncthreads();
    float* o_s  = reg;     // 8192 floats (tiled_nk, rows=n, k=channel)
    float* pw_s = w_s;     // 16384 floats (tiled_nk, rows=j, k=channel)

#pragma unroll
    for (int nt = 0; nt < 4; nt++) {
        const int d0 = h * 32 + nt * 8 + 2 * cth;
        o_s[tiled_nk(n_lo, d0    )] = to_tf32(oacc[nt][0]);
        o_s[tiled_nk(n_lo, d0 + 1)] = to_tf32(oacc[nt][1]);
        o_s[tiled_nk(n_hi, d0    )] = to_tf32(oacc[nt][2]);
        o_s[tiled_nk(n_hi, d0 + 1)] = to_tf32(oacc[nt][3]);
    }
    for (int idx = t; idx < 4096; idx += 512) {
        const int j = idx >> 5, k4 = (idx & 31) * 4;
        const float4 w = *(const float4*)(pw + j * DIM + k4);
        pw_s[tiled_nk(j, k4 + 0)] = to_tf32(w.x);
        pw_s[tiled_nk(j, k4 + 1)] = to_tf32(w.y);
        pw_s[tiled_nk(j, k4 + 2)] = to_tf32(w.z);
        pw_s[tiled_nk(j, k4 + 3)] = to_tf32(w.w);
    }
    __syncthreads();

    // proj: warp w -> rows (w&3)*16, out-cols (w>>2)*32; 64 mma
    const int slab  = (wid & 3) * 16;
    const int jbase = (wid >> 2) * 32;
    float pc[4][4];
#pragma unroll
    for (int nt = 0; nt < 4; nt++)
#pragma unroll
        for (int j = 0; j < 4; j++) pc[nt][j] = 0.f;

#pragma unroll
    for (int kt = 0; kt < 16; kt++) {
        const float2 alo = *(const float2*)&o_s[(((slab >> 3)    ) * 16 + kt) * 64 + ldoff];
        const float2 ahi = *(const float2*)&o_s[(((slab >> 3) + 1) * 16 + kt) * 64 + ldoff];
        const uint32_t a0 = __float_as_uint(alo.x);
        const uint32_t a1 = __float_as_uint(ahi.x);
        const uint32_t a2 = __float_as_uint(alo.y);
        const uint32_t a3 = __float_as_uint(ahi.y);
#pragma unroll
        for (int nt = 0; nt < 4; nt++) {
            const float2 bp = *(const float2*)&pw_s[(((jbase >> 3) + nt) * 16 + kt) * 64 + ldoff];
            mma_tf32(pc[nt], a0, a1, a2, a3,
                     __float_as_uint(bp.x), __float_as_uint(bp.y));
        }
    }

    float* xo = out + (size_t)bdst * (NTOK * DIM);
    const int prow = slab + r0;
#pragma unroll
    for (int nt = 0; nt < 4; nt++) {
        const int col0 = jbase + nt * 8 + 2 * cth;
        const float2 bv = *(const float2*)(pb + col0);
        *(float2*)&xo[prow * DIM + col0] =
            make_float2(pc[nt][0] + bv.x, pc[nt][1] + bv.y);
        *(float2*)&xo[(prow + 8) * DIM + col0] =
            make_float2(pc[nt][2] + bv.x, pc[nt][3] + bv.y);
    }
}

// ---------------------------------------------------------------------------
extern "C" void kernel_launch(void* const* d_in, const int* in_sizes, int n_in,
                              void* d_out, int out_size)
{
    const float* x1     = (const float*)d_in[0];
    const float* x2     = (const float*)d_in[1];
    const float* qkv1_w = (const float*)d_in[2];
    const float* qkv1_b = (const float*)d_in[3];
    const float* qkv2_w = (const float*)d_in[4];
    const float* qkv2_b = (const float*)d_in[5];
    const float* proj_w = (const float*)d_in[6];
    const float* proj_b = (const float*)d_in[7];
    const float* rpb    = (const float*)d_in[8];
    const int*   rel    = (const int*)d_in[9];
    float* out = (float*)d_out;

    static bool attr_set = false;
    if (!attr_set) {
        cudaFuncSetAttribute(q_kernel,
                             cudaFuncAttributeMaxDynamicSharedMemorySize,
                             QK_SMEM_FLOATS * sizeof(float));
        cudaFuncSetAttribute(fused_kernel,
                             cudaFuncAttributeMaxDynamicSharedMemorySize,
                             FUSED_SMEM_FLOATS * sizeof(float));
        attr_set = true;
    }

    q_kernel<<<B1N, 256, QK_SMEM_FLOATS * sizeof(float)>>>(x1, qkv1_w, qkv1_b);
    fused_kernel<<<B1N, 512, FUSED_SMEM_FLOATS * sizeof(float)>>>(
        x2, qkv2_w, qkv2_b, proj_w, proj_b, rpb, rel, out);
}

// round 12
// speedup vs baseline: 1.0326x; 1.0326x over previous
#include <cuda_runtime.h>
#include <cstdint>

#define NTOK 64
#define DIM  128
#define B1N  2048
#define B2N  8192
#define QSCALE 0.17677669529663687f
#define X_ELEMS 16777216   // B1N*NTOK*DIM

// Tiled scratch layouts (8x8 tiles, 64 floats each):
//  g_Q[b][8192]:  tile=(n>>3)*16+(k>>3), pos=(n&7)*8+2*(k&3)+((k&4)>>2)
//  g_KV[b2][16384]: K half [0,8192) same as Q with (m,d);
//                   V half [8192,16384): tile=(m>>3)*16+(d>>3),
//                                        pos=(d&7)*8+2*(m&3)+((m&4)>>2)
__device__ float g_Q[(size_t)B1N * 8192];
__device__ float g_KV[(size_t)B2N * 16384];

__device__ __forceinline__ float to_tf32(float x) {
    float r; asm("cvt.rna.tf32.f32 %0, %1;" : "=f"(r) : "f"(x)); return r;
}
__device__ __forceinline__ void mma_tf32(float c[4],
    uint32_t a0, uint32_t a1, uint32_t a2, uint32_t a3,
    uint32_t b0, uint32_t b1)
{
    asm volatile(
        "mma.sync.aligned.m16n8k8.row.col.f32.tf32.tf32.f32 "
        "{%0,%1,%2,%3},{%4,%5,%6,%7},{%8,%9},{%0,%1,%2,%3};"
        : "+f"(c[0]), "+f"(c[1]), "+f"(c[2]), "+f"(c[3])
        : "r"(a0), "r"(a1), "r"(a2), "r"(a3), "r"(b0), "r"(b1));
}

__device__ __forceinline__ int tiled_nk(int n, int k) {   // Q/K/W/A layout
    return ((n >> 3) * 16 + (k >> 3)) * 64 + (n & 7) * 8 + 2 * (k & 3) + ((k & 4) >> 2);
}
__device__ __forceinline__ int tiled_v(int m, int d) {    // V layout
    return ((m >> 3) * 16 + (d >> 3)) * 64 + (d & 7) * 8 + 2 * (m & 3) + ((m & 4) >> 2);
}

__device__ __forceinline__ uint32_t smem_u32(const void* p) {
    return (uint32_t)__cvta_generic_to_shared(p);
}
__device__ __forceinline__ void cp16(uint32_t dst, const void* src) {
    asm volatile("cp.async.cg.shared.global [%0], [%1], 16;" :: "r"(dst), "l"(src));
}
#define CP_COMMIT() asm volatile("cp.async.commit_group;")
#define CP_WAIT0()  asm volatile("cp.async.wait_group 0;")
#define CP_WAIT1()  asm volatile("cp.async.wait_group 1;")

// ---------------------------------------------------------------------------
// Kernel B (first -> profile slot): KV = tf32( x2 @ W2^T + b2 ),
// W2 CTA-resident (tiled), 8 windows/CTA. R12: x2 staged TILED -> A = LDS.64.
// 512 threads, 16 warps: warp w -> m-tile (w&3)*16, n-base (w>>2)*64.
// ---------------------------------------------------------------------------
#define KV_GW 8
#define KV_SMEM_FLOATS (32768 + 2 * 8192)   // w_tiled + x2 tiled double buffer

__global__ void __launch_bounds__(512, 1) kv_kernel(
    const float* __restrict__ x2, const float* __restrict__ w2,
    const float* __restrict__ bias2)
{
    extern __shared__ float sm[];
    float* w_s = sm;

    const int t = threadIdx.x;
    const int lane = t & 31, wid = t >> 5;
    const int m_base = (wid & 3) * 16;
    const int n_base = (wid >> 2) * 64;
    const int r0 = lane >> 2, cth = lane & 3;
    const int ldoff = r0 * 8 + 2 * cth;
    const int base = blockIdx.x * KV_GW;

    // stage whole W2 (256x128) once, tiled + tf32
    for (int idx = t; idx < 8192; idx += 512) {
        const int j = idx >> 5, k4 = (idx & 31) * 4;
        const float4 w = *(const float4*)(w2 + j * DIM + k4);
        w_s[tiled_nk(j, k4 + 0)] = to_tf32(w.x);
        w_s[tiled_nk(j, k4 + 1)] = to_tf32(w.y);
        w_s[tiled_nk(j, k4 + 2)] = to_tf32(w.z);
        w_s[tiled_nk(j, k4 + 3)] = to_tf32(w.w);
    }
    // stage x2 window 0, tiled
    {
        const float4* xb = (const float4*)(x2 + (size_t)base * 8192);
        float* a0 = sm + 32768;
        for (int idx = t; idx < 2048; idx += 512) {
            const int m = idx >> 5, k4 = (idx & 31) * 4;
            const float4 v = xb[idx];
            a0[tiled_nk(m, k4 + 0)] = to_tf32(v.x);
            a0[tiled_nk(m, k4 + 1)] = to_tf32(v.y);
            a0[tiled_nk(m, k4 + 2)] = to_tf32(v.z);
            a0[tiled_nk(m, k4 + 3)] = to_tf32(v.w);
        }
    }
    __syncthreads();

    for (int g = 0; g < KV_GW; g++) {
        const int b2 = base + g;
        const float* a_s = sm + 32768 + (g & 1) * 8192;

        // prefetch next window's x2 into registers (hidden by mma)
        float4 pf[4];
        if (g < KV_GW - 1) {
            const float4* xn = (const float4*)(x2 + (size_t)(b2 + 1) * 8192);
#pragma unroll
            for (int i = 0; i < 4; i++) pf[i] = xn[t + i * 512];
        }

        float c[8][4];
#pragma unroll
        for (int nt = 0; nt < 8; nt++)
#pragma unroll
            for (int j = 0; j < 4; j++) c[nt][j] = 0.f;

#pragma unroll
        for (int kt = 0; kt < 16; kt++) {
            const float2 alo = *(const float2*)&a_s[(((m_base >> 3)    ) * 16 + kt) * 64 + ldoff];
            const float2 ahi = *(const float2*)&a_s[(((m_base >> 3) + 1) * 16 + kt) * 64 + ldoff];
            const uint32_t a0 = __float_as_uint(alo.x);
            const uint32_t a1 = __float_as_uint(ahi.x);
            const uint32_t a2 = __float_as_uint(alo.y);
            const uint32_t a3 = __float_as_uint(ahi.y);
#pragma unroll
            for (int nt = 0; nt < 8; nt++) {
                const float2 bp = *(const float2*)&w_s[(((n_base >> 3) + nt) * 16 + kt) * 64 + ldoff];
                mma_tf32(c[nt], a0, a1, a2, a3,
                         __float_as_uint(bp.x), __float_as_uint(bp.y));
            }
        }

        // epilogue: +bias, tf32-round, tiled K/V stores
        float* dst = g_KV + (size_t)b2 * 16384;
        const int row0 = m_base + r0;
#pragma unroll
        for (int nt = 0; nt < 8; nt++) {
            const int col0 = n_base + nt * 8 + 2 * cth;
            const float2 bv = *(const float2*)(bias2 + col0);
            const float v00 = to_tf32(c[nt][0] + bv.x);
            const float v01 = to_tf32(c[nt][1] + bv.y);
            const float v10 = to_tf32(c[nt][2] + bv.x);
            const float v11 = to_tf32(c[nt][3] + bv.y);
            if (col0 < DIM) {
                dst[tiled_nk(row0,     col0    )] = v00;
                dst[tiled_nk(row0,     col0 + 1)] = v01;
                dst[tiled_nk(row0 + 8, col0    )] = v10;
                dst[tiled_nk(row0 + 8, col0 + 1)] = v11;
            } else {
                const int d0 = col0 - DIM;
                dst[8192 + tiled_v(row0,     d0    )] = v00;
                dst[8192 + tiled_v(row0,     d0 + 1)] = v01;
                dst[8192 + tiled_v(row0 + 8, d0    )] = v10;
                dst[8192 + tiled_v(row0 + 8, d0 + 1)] = v11;
            }
        }

        // store prefetched window into alternate buffer (tiled)
        if (g < KV_GW - 1) {
            float* an = sm + 32768 + ((g + 1) & 1) * 8192;
#pragma unroll
            for (int i = 0; i < 4; i++) {
                const int idx = t + i * 512;
                const int m = idx >> 5, k4 = (idx & 31) * 4;
                an[tiled_nk(m, k4 + 0)] = to_tf32(pf[i].x);
                an[tiled_nk(m, k4 + 1)] = to_tf32(pf[i].y);
                an[tiled_nk(m, k4 + 2)] = to_tf32(pf[i].z);
                an[tiled_nk(m, k4 + 3)] = to_tf32(pf[i].w);
            }
        }
        __syncthreads();
    }
}

// ---------------------------------------------------------------------------
// Kernel A: Q = tf32( scale * (x1 @ W1^T + b1) )  [unchanged - committed win]
// ---------------------------------------------------------------------------
#define QK_SMEM_FLOATS (8448 + 4608)

__global__ void __launch_bounds__(256) q_kernel(
    const float* __restrict__ x1, const float* __restrict__ w1,
    const float* __restrict__ bias1)
{
    extern __shared__ float sm[];
    float* a_s = sm;
    float* w_s = sm + 8448;

    const int t = threadIdx.x, b = blockIdx.x;
    const int lane = t & 31, wid = t >> 5;
    const int m_base = (wid & 3) * 16;
    const int n_base = (wid >> 2) * 64;
    const int r0 = lane >> 2, cth = lane & 3;

    const float* xb = x1 + (size_t)b * (NTOK * DIM);
    for (int idx = t; idx < NTOK * DIM; idx += 256) {
        int m = idx >> 7, k = idx & 127;
        a_s[m * 132 + k] = to_tf32(xb[idx]);
    }

    float c[8][4];
#pragma unroll
    for (int nt = 0; nt < 8; nt++)
#pragma unroll
        for (int j = 0; j < 4; j++) c[nt][j] = 0.f;

    for (int kc = 0; kc < 4; kc++) {
        __syncthreads();
        for (int idx = t; idx < 4096; idx += 256) {
            int j = idx >> 5, kk = idx & 31;
            w_s[j * 36 + kk] = to_tf32(w1[j * DIM + kc * 32 + kk]);
        }
        __syncthreads();
#pragma unroll
        for (int ks = 0; ks < 4; ks++) {
            const int col = kc * 32 + ks * 8 + cth;
            const uint32_t a0 = __float_as_uint(a_s[(m_base + r0) * 132 + col]);
            const uint32_t a1 = __float_as_uint(a_s[(m_base + r0 + 8) * 132 + col]);
            const uint32_t a2 = __float_as_uint(a_s[(m_base + r0) * 132 + col + 4]);
            const uint32_t a3 = __float_as_uint(a_s[(m_base + r0 + 8) * 132 + col + 4]);
#pragma unroll
            for (int nt = 0; nt < 8; nt++) {
                const int j = n_base + nt * 8 + r0;
                const uint32_t b0 = __float_as_uint(w_s[j * 36 + ks * 8 + cth]);
                const uint32_t b1 = __float_as_uint(w_s[j * 36 + ks * 8 + 4 + cth]);
                mma_tf32(c[nt], a0, a1, a2, a3, b0, b1);
            }
        }
    }

    float* qb = g_Q + (size_t)b * 8192;
    const int row0 = m_base + r0;
#pragma unroll
    for (int nt = 0; nt < 8; nt++) {
        const int col0 = n_base + nt * 8 + 2 * cth;
        const float2 bv = *(const float2*)(bias1 + col0);
        qb[tiled_nk(row0,     col0    )] = to_tf32((c[nt][0] + bv.x) * QSCALE);
        qb[tiled_nk(row0,     col0 + 1)] = to_tf32((c[nt][1] + bv.y) * QSCALE);
        qb[tiled_nk(row0 + 8, col0    )] = to_tf32((c[nt][2] + bv.x) * QSCALE);
        qb[tiled_nk(row0 + 8, col0 + 1)] = to_tf32((c[nt][3] + bv.y) * QSCALE);
    }
}

// ---------------------------------------------------------------------------
// Kernel C (R10 champion, unchanged): KV double-buffered cp.async staging;
// Q A-frags direct from L2; QK^T / PV / proj via tf32 mma.
// ---------------------------------------------------------------------------
#define STG_SZ 16384                     // k[8192] | v[8192]
#define SMREL (2 * STG_SZ)               // 32768 : uint16[4096] = 2048 floats
#define SMTAB (SMREL + 2048)             // 34816 : 225*4 = 900
#define ATTN_SMEM_FLOATS (SMTAB + 900)   // 35716 floats = 142864 B
// tail: O tiled (8192) in buf0; pw tiled (16384) in buf1

__device__ __forceinline__ void stage_kv(float* buf, int t, int b2)
{
    const float4* kvg = (const float4*)(g_KV + (size_t)b2 * 16384);
#pragma unroll
    for (int i = 0; i < 8; i++) {
        const int idx = t + i * 512;          // 0..4095
        cp16(smem_u32(buf + idx * 4), kvg + idx);
    }
}

__global__ void __launch_bounds__(512, 1) attn_kernel(
    const float* __restrict__ pw, const float* __restrict__ pb,
    const float* __restrict__ rpb, const int* __restrict__ rel,
    float* __restrict__ out)
{
    extern __shared__ float sm[];
    uint16_t* rel_s = (uint16_t*)(sm + SMREL);
    float*    tab_s = sm + SMTAB;

    const int t    = threadIdx.x;
    const int bdst = blockIdx.x;
    const int lane = t & 31, wid = t >> 5;
    const int h  = wid >> 2;
    const int R0 = (wid & 3) * 16;
    const int r0 = lane >> 2, cth = lane & 3;
    const int n_lo = R0 + r0, n_hi = n_lo + 8;
    const int ldoff = r0 * 8 + 2 * cth;

    for (int idx = t; idx < NTOK * NTOK; idx += 512)
        rel_s[idx] = (uint16_t)rel[idx];
    for (int idx = t; idx < 225 * 4; idx += 512)
        tab_s[idx] = rpb[idx];

    {   // prologue: stage KV for r=0
        stage_kv(sm, t, bdst * 4);
        CP_COMMIT();
    }

    float oacc[4][4];
#pragma unroll
    for (int nt = 0; nt < 4; nt++)
#pragma unroll
        for (int j = 0; j < 4; j++) oacc[nt][j] = 0.f;

    for (int r = 0; r < 4; r++) {
        __syncthreads();
        if (r < 3) {
            stage_kv(sm + ((r + 1) & 1) * STG_SZ, t, bdst * 4 + r + 1);
            CP_COMMIT();
        }

        const int b2 = bdst * 4 + r;
        const int qb = b2 & (B1N - 1);
        const float* qg = g_Q + (size_t)qb * 8192;
        float2 qalo[4], qahi[4];
#pragma unroll
        for (int ks = 0; ks < 4; ks++) {
            const int kt = h * 4 + ks;
            qalo[ks] = *(const float2*)&qg[(((R0 >> 3)    ) * 16 + kt) * 64 + ldoff];
            qahi[ks] = *(const float2*)&qg[(((R0 >> 3) + 1) * 16 + kt) * 64 + ldoff];
        }

        if (r < 3) { CP_WAIT1(); } else { CP_WAIT0(); }
        __syncthreads();

        float* k_s = sm + (r & 1) * STG_SZ;
        float* v_s = k_s + 8192;

        float c[8][4];
#pragma unroll
        for (int nt = 0; nt < 8; nt++)
#pragma unroll
            for (int j = 0; j < 4; j++) c[nt][j] = 0.f;

#pragma unroll
        for (int ks = 0; ks < 4; ks++) {
            const int kt = h * 4 + ks;
            const uint32_t a0 = __float_as_uint(qalo[ks].x);
            const uint32_t a1 = __float_as_uint(qahi[ks].x);
            const uint32_t a2 = __float_as_uint(qalo[ks].y);
            const uint32_t a3 = __float_as_uint(qahi[ks].y);
#pragma unroll
            for (int nt = 0; nt < 8; nt++) {
                const float2 bp = *(const float2*)&k_s[(nt * 16 + kt) * 64 + ldoff];
                mma_tf32(c[nt], a0, a1, a2, a3,
                         __float_as_uint(bp.x), __float_as_uint(bp.y));
            }
        }

#pragma unroll
        for (int nt = 0; nt < 8; nt++) {
            const int m = nt * 8 + 2 * cth;
            const uint32_t rlo = *(const uint32_t*)&rel_s[n_lo * 64 + m];
            const uint32_t rhi = *(const uint32_t*)&rel_s[n_hi * 64 + m];
            c[nt][0] += tab_s[(rlo & 0xffff) * 4 + h];
            c[nt][1] += tab_s[(rlo >> 16) * 4 + h];
            c[nt][2] += tab_s[(rhi & 0xffff) * 4 + h];
            c[nt][3] += tab_s[(rhi >> 16) * 4 + h];
        }

        float mx0 = -1e30f, mx1 = -1e30f;
#pragma unroll
        for (int nt = 0; nt < 8; nt++) {
            mx0 = fmaxf(mx0, fmaxf(c[nt][0], c[nt][1]));
            mx1 = fmaxf(mx1, fmaxf(c[nt][2], c[nt][3]));
        }
        mx0 = fmaxf(mx0, __shfl_xor_sync(0xffffffffu, mx0, 1));
        mx0 = fmaxf(mx0, __shfl_xor_sync(0xffffffffu, mx0, 2));
        mx1 = fmaxf(mx1, __shfl_xor_sync(0xffffffffu, mx1, 1));
        mx1 = fmaxf(mx1, __shfl_xor_sync(0xffffffffu, mx1, 2));

        float s0 = 0.f, s1 = 0.f;
#pragma unroll
        for (int nt = 0; nt < 8; nt++) {
            c[nt][0] = __expf(c[nt][0] - mx0); s0 += c[nt][0];
            c[nt][1] = __expf(c[nt][1] - mx0); s0 += c[nt][1];
            c[nt][2] = __expf(c[nt][2] - mx1); s1 += c[nt][2];
            c[nt][3] = __expf(c[nt][3] - mx1); s1 += c[nt][3];
        }
        s0 += __shfl_xor_sync(0xffffffffu, s0, 1);
        s0 += __shfl_xor_sync(0xffffffffu, s0, 2);
        s1 += __shfl_xor_sync(0xffffffffu, s1, 1);
        s1 += __shfl_xor_sync(0xffffffffu, s1, 2);
        const float inv0 = 1.f / s0, inv1 = 1.f / s1;
#pragma unroll
        for (int nt = 0; nt < 8; nt++) {
            c[nt][0] *= inv0; c[nt][1] *= inv0;
            c[nt][2] *= inv1; c[nt][3] *= inv1;
        }

        float* ao = out + (size_t)X_ELEMS + (size_t)b2 * 16384 + h * 4096;
#pragma unroll
        for (int nt = 0; nt < 8; nt++) {
            const int m = nt * 8 + 2 * cth;
            *(float2*)&ao[n_lo * 64 + m] = make_float2(c[nt][0], c[nt][1]);
            *(float2*)&ao[n_hi * 64 + m] = make_float2(c[nt][2], c[nt][3]);
        }

#pragma unroll
        for (int nt = 0; nt < 8; nt++)
#pragma unroll
            for (int j = 0; j < 4; j++) c[nt][j] = to_tf32(c[nt][j]);

        const int src0 = (lane & 28) + (cth >> 1);
        const int src1 = src0 + 2;
        const bool odd = (cth & 1);
#pragma unroll
        for (int ks = 0; ks < 8; ks++) {
            const float e0 = __shfl_sync(0xffffffffu, c[ks][0], src0);
            const float o0 = __shfl_sync(0xffffffffu, c[ks][1], src0);
            const float e2 = __shfl_sync(0xffffffffu, c[ks][0], src1);
            const float o2 = __shfl_sync(0xffffffffu, c[ks][1], src1);
            const float e1 = __shfl_sync(0xffffffffu, c[ks][2], src0);
            const float o1 = __shfl_sync(0xffffffffu, c[ks][3], src0);
            const float e3 = __shfl_sync(0xffffffffu, c[ks][2], src1);
            const float o3 = __shfl_sync(0xffffffffu, c[ks][3], src1);
            const uint32_t pa0 = __float_as_uint(odd ? o0 : e0);
            const uint32_t pa1 = __float_as_uint(odd ? o1 : e1);
            const uint32_t pa2 = __float_as_uint(odd ? o2 : e2);
            const uint32_t pa3 = __float_as_uint(odd ? o3 : e3);
#pragma unroll
            for (int nt = 0; nt < 4; nt++) {
                const float2 bp = *(const float2*)&v_s[(ks * 16 + h * 4 + nt) * 64 + ldoff];
                mma_tf32(oacc[nt], pa0, pa1, pa2, pa3,
                         __float_as_uint(bp.x), __float_as_uint(bp.y));
            }
        }
    } // r

    // tail: O tiled -> buf0, pw tiled -> buf1, proj via tf32 mma
    __syncthreads();
    float* o_s  = sm;
    float* pw_s = sm + STG_SZ;

#pragma unroll
    for (int nt = 0; nt < 4; nt++) {
        const int d0 = h * 32 + nt * 8 + 2 * cth;
        o_s[tiled_nk(n_lo, d0    )] = to_tf32(oacc[nt][0]);
        o_s[tiled_nk(n_lo, d0 + 1)] = to_tf32(oacc[nt][1]);
        o_s[tiled_nk(n_hi, d0    )] = to_tf32(oacc[nt][2]);
        o_s[tiled_nk(n_hi, d0 + 1)] = to_tf32(oacc[nt][3]);
    }
    for (int idx = t; idx < 4096; idx += 512) {
        const int j = idx >> 5, k4 = (idx & 31) * 4;
        const float4 w = *(const float4*)(pw + j * DIM + k4);
        pw_s[tiled_nk(j, k4 + 0)] = to_tf32(w.x);
        pw_s[tiled_nk(j, k4 + 1)] = to_tf32(w.y);
        pw_s[tiled_nk(j, k4 + 2)] = to_tf32(w.z);
        pw_s[tiled_nk(j, k4 + 3)] = to_tf32(w.w);
    }
    __syncthreads();

    const int slab  = (wid & 3) * 16;
    const int jbase = (wid >> 2) * 32;
    float pc[4][4];
#pragma unroll
    for (int nt = 0; nt < 4; nt++)
#pragma unroll
        for (int j = 0; j < 4; j++) pc[nt][j] = 0.f;

#pragma unroll
    for (int kt = 0; kt < 16; kt++) {
        const float2 alo = *(const float2*)&o_s[(((slab >> 3)    ) * 16 + kt) * 64 + ldoff];
        const float2 ahi = *(const float2*)&o_s[(((slab >> 3) + 1) * 16 + kt) * 64 + ldoff];
        const uint32_t a0 = __float_as_uint(alo.x);
        const uint32_t a1 = __float_as_uint(ahi.x);
        const uint32_t a2 = __float_as_uint(alo.y);
        const uint32_t a3 = __float_as_uint(ahi.y);
#pragma unroll
        for (int nt = 0; nt < 4; nt++) {
            const float2 bp = *(const float2*)&pw_s[(((jbase >> 3) + nt) * 16 + kt) * 64 + ldoff];
            mma_tf32(pc[nt], a0, a1, a2, a3,
                     __float_as_uint(bp.x), __float_as_uint(bp.y));
        }
    }

    float* xo = out + (size_t)bdst * (NTOK * DIM);
    const int prow = slab + r0;
#pragma unroll
    for (int nt = 0; nt < 4; nt++) {
        const int col0 = jbase + nt * 8 + 2 * cth;
        const float2 bv = *(const float2*)(pb + col0);
        *(float2*)&xo[prow * DIM + col0] =
            make_float2(pc[nt][0] + bv.x, pc[nt][1] + bv.y);
        *(float2*)&xo[(prow + 8) * DIM + col0] =
            make_float2(pc[nt][2] + bv.x, pc[nt][3] + bv.y);
    }
}

// ---------------------------------------------------------------------------
extern "C" void kernel_launch(void* const* d_in, const int* in_sizes, int n_in,
                              void* d_out, int out_size)
{
    const float* x1     = (const float*)d_in[0];
    const float* x2     = (const float*)d_in[1];
    const float* qkv1_w = (const float*)d_in[2];
    const float* qkv1_b = (const float*)d_in[3];
    const float* qkv2_w = (const float*)d_in[4];
    const float* qkv2_b = (const float*)d_in[5];
    const float* proj_w = (const float*)d_in[6];
    const float* proj_b = (const float*)d_in[7];
    const float* rpb    = (const float*)d_in[8];
    const int*   rel    = (const int*)d_in[9];
    float* out = (float*)d_out;

    static bool attr_set = false;
    if (!attr_set) {
        cudaFuncSetAttribute(q_kernel,
                             cudaFuncAttributeMaxDynamicSharedMemorySize,
                             QK_SMEM_FLOATS * sizeof(float));
        cudaFuncSetAttribute(kv_kernel,
                             cudaFuncAttributeMaxDynamicSharedMemorySize,
                             KV_SMEM_FLOATS * sizeof(float));
        cudaFuncSetAttribute(attn_kernel,
                             cudaFuncAttributeMaxDynamicSharedMemorySize,
                             ATTN_SMEM_FLOATS * sizeof(float));
        attr_set = true;
    }

    kv_kernel<<<B2N / KV_GW, 512, KV_SMEM_FLOATS * sizeof(float)>>>(x2, qkv2_w, qkv2_b);
    q_kernel<<<B1N, 256, QK_SMEM_FLOATS * sizeof(float)>>>(x1, qkv1_w, qkv1_b);
    attn_kernel<<<B1N, 512, ATTN_SMEM_FLOATS * sizeof(float)>>>(
        proj_w, proj_b, rpb, rel, out);
}

// round 15
// speedup vs baseline: 1.1567x; 1.1202x over previous
#include <cuda_runtime.h>
#include <cstdint>

#define NTOK 64
#define DIM  128
#define B1N  2048
#define B2N  8192
#define QSCALE 0.17677669529663687f
#define X_ELEMS 16777216   // B1N*NTOK*DIM

// Tiled scratch layouts (8x8 tiles, 64 floats each):
//  g_Q[b][8192]:  tile=(n>>3)*16+(k>>3), pos=(n&7)*8+2*(k&3)+((k&4)>>2)
//  g_KV[b2][16384]: K half [0,8192) same as Q with (m,d);
//                   V half [8192,16384): tile=(m>>3)*16+(d>>3),
//                                        pos=(d&7)*8+2*(m&3)+((m&4)>>2)
__device__ float g_Q[(size_t)B1N * 8192];
__device__ float g_KV[(size_t)B2N * 16384];

__device__ __forceinline__ float to_tf32(float x) {
    float r; asm("cvt.rna.tf32.f32 %0, %1;" : "=f"(r) : "f"(x)); return r;
}
__device__ __forceinline__ void mma_tf32(float c[4],
    uint32_t a0, uint32_t a1, uint32_t a2, uint32_t a3,
    uint32_t b0, uint32_t b1)
{
    asm volatile(
        "mma.sync.aligned.m16n8k8.row.col.f32.tf32.tf32.f32 "
        "{%0,%1,%2,%3},{%4,%5,%6,%7},{%8,%9},{%0,%1,%2,%3};"
        : "+f"(c[0]), "+f"(c[1]), "+f"(c[2]), "+f"(c[3])
        : "r"(a0), "r"(a1), "r"(a2), "r"(a3), "r"(b0), "r"(b1));
}

__device__ __forceinline__ int tiled_nk(int n, int k) {   // Q/K/W layout
    return ((n >> 3) * 16 + (k >> 3)) * 64 + (n & 7) * 8 + 2 * (k & 3) + ((k & 4) >> 2);
}
__device__ __forceinline__ int tiled_v(int m, int d) {    // V layout
    return ((m >> 3) * 16 + (d >> 3)) * 64 + (d & 7) * 8 + 2 * (m & 3) + ((m & 4) >> 2);
}

__device__ __forceinline__ uint32_t smem_u32(const void* p) {
    return (uint32_t)__cvta_generic_to_shared(p);
}
__device__ __forceinline__ void cp16(uint32_t dst, const void* src) {
    asm volatile("cp.async.cg.shared.global [%0], [%1], 16;" :: "r"(dst), "l"(src));
}
#define CP_COMMIT() asm volatile("cp.async.commit_group;")
#define CP_WAIT0()  asm volatile("cp.async.wait_group 0;")
#define CP_WAIT1()  asm volatile("cp.async.wait_group 1;")

// ---------------------------------------------------------------------------
// Kernel B (first -> profile slot): KV = tf32( x2 @ W2^T + b2 ),
// W2 CTA-resident (tiled), 8 windows/CTA.
// R13: x2 staged via cp.async (raw fp32; mma truncates to tf32) -> no
// LDG/cvt/STS register round-trip.  Stride-132 staging layout (R9 proven).
// 512 threads, 16 warps: warp w -> m-tile (w&3)*16, n-base (w>>2)*64.
// ---------------------------------------------------------------------------
#define KV_GW 8
#define KV_SMEM_FLOATS (32768 + 2 * 8448)   // w_tiled + a_s double buffer (stride 132)

__global__ void __launch_bounds__(512, 1) kv_kernel(
    const float* __restrict__ x2, const float* __restrict__ w2,
    const float* __restrict__ bias2)
{
    extern __shared__ float sm[];
    float* w_s = sm;             // tiled W2: 32768 floats

    const int t = threadIdx.x;
    const int lane = t & 31, wid = t >> 5;
    const int m_base = (wid & 3) * 16;
    const int n_base = (wid >> 2) * 64;
    const int r0 = lane >> 2, cth = lane & 3;
    const int base = blockIdx.x * KV_GW;

    // stage whole W2 (256x128) once, tiled + tf32(rna)
    for (int idx = t; idx < 8192; idx += 512) {
        const int j = idx >> 5, k4 = (idx & 31) * 4;
        const float4 w = *(const float4*)(w2 + j * DIM + k4);
        w_s[tiled_nk(j, k4 + 0)] = to_tf32(w.x);
        w_s[tiled_nk(j, k4 + 1)] = to_tf32(w.y);
        w_s[tiled_nk(j, k4 + 2)] = to_tf32(w.z);
        w_s[tiled_nk(j, k4 + 3)] = to_tf32(w.w);
    }

    // prologue: cp.async stage x2 window 0 into buf0 (raw fp32)
    {
        const float* xb = x2 + (size_t)base * 8192;
        float* a0 = sm + 32768;
#pragma unroll
        for (int i = 0; i < 4; i++) {
            const int idx = t + i * 512;          // 0..2047 float4 chunks
            const int m = idx >> 5, k4 = (idx & 31) * 4;
            cp16(smem_u32(a0 + m * 132 + k4), xb + m * DIM + k4);
        }
        CP_COMMIT();
    }

    for (int g = 0; g < KV_GW; g++) {
        const int b2 = base + g;

        __syncthreads();   // all warps done reading buf[(g+1)&1] (window g-1)
        if (g < KV_GW - 1) {
            const float* xn = x2 + (size_t)(b2 + 1) * 8192;
            float* an = sm + 32768 + ((g + 1) & 1) * 8448;
#pragma unroll
            for (int i = 0; i < 4; i++) {
                const int idx = t + i * 512;
                const int m = idx >> 5, k4 = (idx & 31) * 4;
                cp16(smem_u32(an + m * 132 + k4), xn + m * DIM + k4);
            }
            CP_COMMIT();
            CP_WAIT1();    // window g arrived (g+1 still in flight)
        } else {
            CP_WAIT0();
        }
        __syncthreads();   // window g visible to all

        const float* a_s = sm + 32768 + (g & 1) * 8448;

        float c[8][4];
#pragma unroll
        for (int nt = 0; nt < 8; nt++)
#pragma unroll
            for (int j = 0; j < 4; j++) c[nt][j] = 0.f;

#pragma unroll
        for (int kc = 0; kc < 4; kc++) {
#pragma unroll
            for (int ks = 0; ks < 4; ks++) {
                const int col = kc * 32 + ks * 8 + cth;
                const uint32_t a0 = __float_as_uint(a_s[(m_base + r0) * 132 + col]);
                const uint32_t a1 = __float_as_uint(a_s[(m_base + r0 + 8) * 132 + col]);
                const uint32_t a2 = __float_as_uint(a_s[(m_base + r0) * 132 + col + 4]);
                const uint32_t a3 = __float_as_uint(a_s[(m_base + r0 + 8) * 132 + col + 4]);
                const int ktile = kc * 4 + ks;
#pragma unroll
                for (int nt = 0; nt < 8; nt++) {
                    const int tile = ((n_base >> 3) + nt) * 16 + ktile;
                    const float2 bp = *(const float2*)&w_s[tile * 64 + r0 * 8 + 2 * cth];
                    mma_tf32(c[nt], a0, a1, a2, a3,
                             __float_as_uint(bp.x), __float_as_uint(bp.y));
                }
            }
        }

        // epilogue: +bias, tf32(rna)-round, tiled K/V stores
        float* dst = g_KV + (size_t)b2 * 16384;
        const int row0 = m_base + r0;
#pragma unroll
        for (int nt = 0; nt < 8; nt++) {
            const int col0 = n_base + nt * 8 + 2 * cth;
            const float2 bv = *(const float2*)(bias2 + col0);
            const float v00 = to_tf32(c[nt][0] + bv.x);
            const float v01 = to_tf32(c[nt][1] + bv.y);
            const float v10 = to_tf32(c[nt][2] + bv.x);
            const float v11 = to_tf32(c[nt][3] + bv.y);
            if (col0 < DIM) {
                dst[tiled_nk(row0,     col0    )] = v00;
                dst[tiled_nk(row0,     col0 + 1)] = v01;
                dst[tiled_nk(row0 + 8, col0    )] = v10;
                dst[tiled_nk(row0 + 8, col0 + 1)] = v11;
            } else {
                const int d0 = col0 - DIM;
                dst[8192 + tiled_v(row0,     d0    )] = v00;
                dst[8192 + tiled_v(row0,     d0 + 1)] = v01;
                dst[8192 + tiled_v(row0 + 8, d0    )] = v10;
                dst[8192 + tiled_v(row0 + 8, d0 + 1)] = v11;
            }
        }
    }
}

// ---------------------------------------------------------------------------
// Kernel A: Q = tf32( scale * (x1 @ W1^T + b1) )  [unchanged - committed win]
// ---------------------------------------------------------------------------
#define QK_SMEM_FLOATS (8448 + 4608)

__global__ void __launch_bounds__(256) q_kernel(
    const float* __restrict__ x1, const float* __restrict__ w1,
    const float* __restrict__ bias1)
{
    extern __shared__ float sm[];
    float* a_s = sm;
    float* w_s = sm + 8448;

    const int t = threadIdx.x, b = blockIdx.x;
    const int lane = t & 31, wid = t >> 5;
    const int m_base = (wid & 3) * 16;
    const int n_base = (wid >> 2) * 64;
    const int r0 = lane >> 2, cth = lane & 3;

    const float* xb = x1 + (size_t)b * (NTOK * DIM);
    for (int idx = t; idx < NTOK * DIM; idx += 256) {
        int m = idx >> 7, k = idx & 127;
        a_s[m * 132 + k] = to_tf32(xb[idx]);
    }

    float c[8][4];
#pragma unroll
    for (int nt = 0; nt < 8; nt++)
#pragma unroll
        for (int j = 0; j < 4; j++) c[nt][j] = 0.f;

    for (int kc = 0; kc < 4; kc++) {
        __syncthreads();
        for (int idx = t; idx < 4096; idx += 256) {
            int j = idx >> 5, kk = idx & 31;
            w_s[j * 36 + kk] = to_tf32(w1[j * DIM + kc * 32 + kk]);
        }
        __syncthreads();
#pragma unroll
        for (int ks = 0; ks < 4; ks++) {
            const int col = kc * 32 + ks * 8 + cth;
            const uint32_t a0 = __float_as_uint(a_s[(m_base + r0) * 132 + col]);
            const uint32_t a1 = __float_as_uint(a_s[(m_base + r0 + 8) * 132 + col]);
            const uint32_t a2 = __float_as_uint(a_s[(m_base + r0) * 132 + col + 4]);
            const uint32_t a3 = __float_as_uint(a_s[(m_base + r0 + 8) * 132 + col + 4]);
#pragma unroll
            for (int nt = 0; nt < 8; nt++) {
                const int j = n_base + nt * 8 + r0;
                const uint32_t b0 = __float_as_uint(w_s[j * 36 + ks * 8 + cth]);
                const uint32_t b1 = __float_as_uint(w_s[j * 36 + ks * 8 + 4 + cth]);
                mma_tf32(c[nt], a0, a1, a2, a3, b0, b1);
            }
        }
    }

    float* qb = g_Q + (size_t)b * 8192;
    const int row0 = m_base + r0;
#pragma unroll
    for (int nt = 0; nt < 8; nt++) {
        const int col0 = n_base + nt * 8 + 2 * cth;
        const float2 bv = *(const float2*)(bias1 + col0);
        qb[tiled_nk(row0,     col0    )] = to_tf32((c[nt][0] + bv.x) * QSCALE);
        qb[tiled_nk(row0,     col0 + 1)] = to_tf32((c[nt][1] + bv.y) * QSCALE);
        qb[tiled_nk(row0 + 8, col0    )] = to_tf32((c[nt][2] + bv.x) * QSCALE);
        qb[tiled_nk(row0 + 8, col0 + 1)] = to_tf32((c[nt][3] + bv.y) * QSCALE);
    }
}

// ---------------------------------------------------------------------------
// Kernel C (R10 champion, unchanged): KV double-buffered cp.async staging;
// Q A-frags direct from L2; QK^T / PV / proj via tf32 mma.
// ---------------------------------------------------------------------------
#define STG_SZ 16384                     // k[8192] | v[8192]
#define SMREL (2 * STG_SZ)               // 32768 : uint16[4096] = 2048 floats
#define SMTAB (SMREL + 2048)             // 34816 : 225*4 = 900
#define ATTN_SMEM_FLOATS (SMTAB + 900)   // 35716 floats = 142864 B
// tail: O tiled (8192) in buf0; pw tiled (16384) in buf1

__device__ __forceinline__ void stage_kv(float* buf, int t, int b2)
{
    const float4* kvg = (const float4*)(g_KV + (size_t)b2 * 16384);
#pragma unroll
    for (int i = 0; i < 8; i++) {
        const int idx = t + i * 512;          // 0..4095
        cp16(smem_u32(buf + idx * 4), kvg + idx);
    }
}

__global__ void __launch_bounds__(512, 1) attn_kernel(
    const float* __restrict__ pw, const float* __restrict__ pb,
    const float* __restrict__ rpb, const int* __restrict__ rel,
    float* __restrict__ out)
{
    extern __shared__ float sm[];
    uint16_t* rel_s = (uint16_t*)(sm + SMREL);
    float*    tab_s = sm + SMTAB;

    const int t    = threadIdx.x;
    const int bdst = blockIdx.x;
    const int lane = t & 31, wid = t >> 5;
    const int h  = wid >> 2;
    const int R0 = (wid & 3) * 16;
    const int r0 = lane >> 2, cth = lane & 3;
    const int n_lo = R0 + r0, n_hi = n_lo + 8;
    const int ldoff = r0 * 8 + 2 * cth;

    for (int idx = t; idx < NTOK * NTOK; idx += 512)
        rel_s[idx] = (uint16_t)rel[idx];
    for (int idx = t; idx < 225 * 4; idx += 512)
        tab_s[idx] = rpb[idx];

    {   // prologue: stage KV for r=0
        stage_kv(sm, t, bdst * 4);
        CP_COMMIT();
    }

    float oacc[4][4];
#pragma unroll
    for (int nt = 0; nt < 4; nt++)
#pragma unroll
        for (int j = 0; j < 4; j++) oacc[nt][j] = 0.f;

    for (int r = 0; r < 4; r++) {
        __syncthreads();
        if (r < 3) {
            stage_kv(sm + ((r + 1) & 1) * STG_SZ, t, bdst * 4 + r + 1);
            CP_COMMIT();
        }

        const int b2 = bdst * 4 + r;
        const int qb = b2 & (B1N - 1);
        const float* qg = g_Q + (size_t)qb * 8192;
        float2 qalo[4], qahi[4];
#pragma unroll
        for (int ks = 0; ks < 4; ks++) {
            const int kt = h * 4 + ks;
            qalo[ks] = *(const float2*)&qg[(((R0 >> 3)    ) * 16 + kt) * 64 + ldoff];
            qahi[ks] = *(const float2*)&qg[(((R0 >> 3) + 1) * 16 + kt) * 64 + ldoff];
        }

        if (r < 3) { CP_WAIT1(); } else { CP_WAIT0(); }
        __syncthreads();

        float* k_s = sm + (r & 1) * STG_SZ;
        float* v_s = k_s + 8192;

        float c[8][4];
#pragma unroll
        for (int nt = 0; nt < 8; nt++)
#pragma unroll
            for (int j = 0; j < 4; j++) c[nt][j] = 0.f;

#pragma unroll
        for (int ks = 0; ks < 4; ks++) {
            const int kt = h * 4 + ks;
            const uint32_t a0 = __float_as_uint(qalo[ks].x);
            const uint32_t a1 = __float_as_uint(qahi[ks].x);
            const uint32_t a2 = __float_as_uint(qalo[ks].y);
            const uint32_t a3 = __float_as_uint(qahi[ks].y);
#pragma unroll
            for (int nt = 0; nt < 8; nt++) {
                const float2 bp = *(const float2*)&k_s[(nt * 16 + kt) * 64 + ldoff];
                mma_tf32(c[nt], a0, a1, a2, a3,
                         __float_as_uint(bp.x), __float_as_uint(bp.y));
            }
        }

#pragma unroll
        for (int nt = 0; nt < 8; nt++) {
            const int m = nt * 8 + 2 * cth;
            const uint32_t rlo = *(const uint32_t*)&rel_s[n_lo * 64 + m];
            const uint32_t rhi = *(const uint32_t*)&rel_s[n_hi * 64 + m];
            c[nt][0] += tab_s[(rlo & 0xffff) * 4 + h];
            c[nt][1] += tab_s[(rlo >> 16) * 4 + h];
            c[nt][2] += tab_s[(rhi & 0xffff) * 4 + h];
            c[nt][3] += tab_s[(rhi >> 16) * 4 + h];
        }

        float mx0 = -1e30f, mx1 = -1e30f;
#pragma unroll
        for (int nt = 0; nt < 8; nt++) {
            mx0 = fmaxf(mx0, fmaxf(c[nt][0], c[nt][1]));
            mx1 = fmaxf(mx1, fmaxf(c[nt][2], c[nt][3]));
        }
        mx0 = fmaxf(mx0, __shfl_xor_sync(0xffffffffu, mx0, 1));
        mx0 = fmaxf(mx0, __shfl_xor_sync(0xffffffffu, mx0, 2));
        mx1 = fmaxf(mx1, __shfl_xor_sync(0xffffffffu, mx1, 1));
        mx1 = fmaxf(mx1, __shfl_xor_sync(0xffffffffu, mx1, 2));

        float s0 = 0.f, s1 = 0.f;
#pragma unroll
        for (int nt = 0; nt < 8; nt++) {
            c[nt][0] = __expf(c[nt][0] - mx0); s0 += c[nt][0];
            c[nt][1] = __expf(c[nt][1] - mx0); s0 += c[nt][1];
            c[nt][2] = __expf(c[nt][2] - mx1); s1 += c[nt][2];
            c[nt][3] = __expf(c[nt][3] - mx1); s1 += c[nt][3];
        }
        s0 += __shfl_xor_sync(0xffffffffu, s0, 1);
        s0 += __shfl_xor_sync(0xffffffffu, s0, 2);
        s1 += __shfl_xor_sync(0xffffffffu, s1, 1);
        s1 += __shfl_xor_sync(0xffffffffu, s1, 2);
        const float inv0 = 1.f / s0, inv1 = 1.f / s1;
#pragma unroll
        for (int nt = 0; nt < 8; nt++) {
            c[nt][0] *= inv0; c[nt][1] *= inv0;
            c[nt][2] *= inv1; c[nt][3] *= inv1;
        }

        float* ao = out + (size_t)X_ELEMS + (size_t)b2 * 16384 + h * 4096;
#pragma unroll
        for (int nt = 0; nt < 8; nt++) {
            const int m = nt * 8 + 2 * cth;
            *(float2*)&ao[n_lo * 64 + m] = make_float2(c[nt][0], c[nt][1]);
            *(float2*)&ao[n_hi * 64 + m] = make_float2(c[nt][2], c[nt][3]);
        }

#pragma unroll
        for (int nt = 0; nt < 8; nt++)
#pragma unroll
            for (int j = 0; j < 4; j++) c[nt][j] = to_tf32(c[nt][j]);

        const int src0 = (lane & 28) + (cth >> 1);
        const int src1 = src0 + 2;
        const bool odd = (cth & 1);
#pragma unroll
        for (int ks = 0; ks < 8; ks++) {
            const float e0 = __shfl_sync(0xffffffffu, c[ks][0], src0);
            const float o0 = __shfl_sync(0xffffffffu, c[ks][1], src0);
            const float e2 = __shfl_sync(0xffffffffu, c[ks][0], src1);
            const float o2 = __shfl_sync(0xffffffffu, c[ks][1], src1);
            const float e1 = __shfl_sync(0xffffffffu, c[ks][2], src0);
            const float o1 = __shfl_sync(0xffffffffu, c[ks][3], src0);
            const float e3 = __shfl_sync(0xffffffffu, c[ks][2], src1);
            const float o3 = __shfl_sync(0xffffffffu, c[ks][3], src1);
            const uint32_t pa0 = __float_as_uint(odd ? o0 : e0);
            const uint32_t pa1 = __float_as_uint(odd ? o1 : e1);
            const uint32_t pa2 = __float_as_uint(odd ? o2 : e2);
            const uint32_t pa3 = __float_as_uint(odd ? o3 : e3);
#pragma unroll
            for (int nt = 0; nt < 4; nt++) {
                const float2 bp = *(const float2*)&v_s[(ks * 16 + h * 4 + nt) * 64 + ldoff];
                mma_tf32(oacc[nt], pa0, pa1, pa2, pa3,
                         __float_as_uint(bp.x), __float_as_uint(bp.y));
            }
        }
    } // r

    // tail: O tiled -> buf0, pw tiled -> buf1, proj via tf32 mma
    __syncthreads();
    float* o_s  = sm;
    float* pw_s = sm + STG_SZ;

#pragma unroll
    for (int nt = 0; nt < 4; nt++) {
        const int d0 = h * 32 + nt * 8 + 2 * cth;
        o_s[tiled_nk(n_lo, d0    )] = to_tf32(oacc[nt][0]);
        o_s[tiled_nk(n_lo, d0 + 1)] = to_tf32(oacc[nt][1]);
        o_s[tiled_nk(n_hi, d0    )] = to_tf32(oacc[nt][2]);
        o_s[tiled_nk(n_hi, d0 + 1)] = to_tf32(oacc[nt][3]);
    }
    for (int idx = t; idx < 4096; idx += 512) {
        const int j = idx >> 5, k4 = (idx & 31) * 4;
        const float4 w = *(const float4*)(pw + j * DIM + k4);
        pw_s[tiled_nk(j, k4 + 0)] = to_tf32(w.x);
        pw_s[tiled_nk(j, k4 + 1)] = to_tf32(w.y);
        pw_s[tiled_nk(j, k4 + 2)] = to_tf32(w.z);
        pw_s[tiled_nk(j, k4 + 3)] = to_tf32(w.w);
    }
    __syncthreads();

    const int slab  = (wid & 3) * 16;
    const int jbase = (wid >> 2) * 32;
    float pc[4][4];
#pragma unroll
    for (int nt = 0; nt < 4; nt++)
#pragma unroll
        for (int j = 0; j < 4; j++) pc[nt][j] = 0.f;

#pragma unroll
    for (int kt = 0; kt < 16; kt++) {
        const float2 alo = *(const float2*)&o_s[(((slab >> 3)    ) * 16 + kt) * 64 + ldoff];
        const float2 ahi = *(const float2*)&o_s[(((slab >> 3) + 1) * 16 + kt) * 64 + ldoff];
        const uint32_t a0 = __float_as_uint(alo.x);
        const uint32_t a1 = __float_as_uint(ahi.x);
        const uint32_t a2 = __float_as_uint(alo.y);
        const uint32_t a3 = __float_as_uint(ahi.y);
#pragma unroll
        for (int nt = 0; nt < 4; nt++) {
            const float2 bp = *(const float2*)&pw_s[(((jbase >> 3) + nt) * 16 + kt) * 64 + ldoff];
            mma_tf32(pc[nt], a0, a1, a2, a3,
                     __float_as_uint(bp.x), __float_as_uint(bp.y));
        }
    }

    float* xo = out + (size_t)bdst * (NTOK * DIM);
    const int prow = slab + r0;
#pragma unroll
    for (int nt = 0; nt < 4; nt++) {
        const int col0 = jbase + nt * 8 + 2 * cth;
        const float2 bv = *(const float2*)(pb + col0);
        *(float2*)&xo[prow * DIM + col0] =
            make_float2(pc[nt][0] + bv.x, pc[nt][1] + bv.y);
        *(float2*)&xo[(prow + 8) * DIM + col0] =
            make_float2(pc[nt][2] + bv.x, pc[nt][3] + bv.y);
    }
}

// ---------------------------------------------------------------------------
extern "C" void kernel_launch(void* const* d_in, const int* in_sizes, int n_in,
                              void* d_out, int out_size)
{
    const float* x1     = (const float*)d_in[0];
    const float* x2     = (const float*)d_in[1];
    const float* qkv1_w = (const float*)d_in[2];
    const float* qkv1_b = (const float*)d_in[3];
    const float* qkv2_w = (const float*)d_in[4];
    const float* qkv2_b = (const float*)d_in[5];
    const float* proj_w = (const float*)d_in[6];
    const float* proj_b = (const float*)d_in[7];
    const float* rpb    = (const float*)d_in[8];
    const int*   rel    = (const int*)d_in[9];
    float* out = (float*)d_out;

    static bool attr_set = false;
    if (!attr_set) {
        cudaFuncSetAttribute(q_kernel,
                             cudaFuncAttributeMaxDynamicSharedMemorySize,
                             QK_SMEM_FLOATS * sizeof(float));
        cudaFuncSetAttribute(kv_kernel,
                             cudaFuncAttributeMaxDynamicSharedMemorySize,
                             KV_SMEM_FLOATS * sizeof(float));
        cudaFuncSetAttribute(attn_kernel,
                             cudaFuncAttributeMaxDynamicSharedMemorySize,
                             ATTN_SMEM_FLOATS * sizeof(float));
        attr_set = true;
    }

    kv_kernel<<<B2N / KV_GW, 512, KV_SMEM_FLOATS * sizeof(float)>>>(x2, qkv2_w, qkv2_b);
    q_kernel<<<B1N, 256, QK_SMEM_FLOATS * sizeof(float)>>>(x1, qkv1_w, qkv1_b);
    attn_kernel<<<B1N, 512, ATTN_SMEM_FLOATS * sizeof(float)>>>(
        proj_w, proj_b, rpb, rel, out);
}

// round 16
// speedup vs baseline: 1.2076x; 1.0440x over previous
#include <cuda_runtime.h>
#include <cstdint>

#define NTOK 64
#define DIM  128
#define B1N  2048
#define B2N  8192
#define QSCALE 0.17677669529663687f
#define X_ELEMS 16777216   // B1N*NTOK*DIM

// Tiled scratch layouts (8x8 tiles, 64 floats each):
//  g_Q[b][8192]:  tile=(n>>3)*16+(k>>3), pos=(n&7)*8+2*(k&3)+((k&4)>>2)
//  g_KV[b2][16384]: K half [0,8192) same as Q with (m,d);
//                   V half [8192,16384): tile=(m>>3)*16+(d>>3),
//                                        pos=(d&7)*8+2*(m&3)+((m&4)>>2)
__device__ float g_Q[(size_t)B1N * 8192];
__device__ float g_KV[(size_t)B2N * 16384];

__device__ __forceinline__ float to_tf32(float x) {
    float r; asm("cvt.rna.tf32.f32 %0, %1;" : "=f"(r) : "f"(x)); return r;
}
__device__ __forceinline__ void mma_tf32(float c[4],
    uint32_t a0, uint32_t a1, uint32_t a2, uint32_t a3,
    uint32_t b0, uint32_t b1)
{
    asm volatile(
        "mma.sync.aligned.m16n8k8.row.col.f32.tf32.tf32.f32 "
        "{%0,%1,%2,%3},{%4,%5,%6,%7},{%8,%9},{%0,%1,%2,%3};"
        : "+f"(c[0]), "+f"(c[1]), "+f"(c[2]), "+f"(c[3])
        : "r"(a0), "r"(a1), "r"(a2), "r"(a3), "r"(b0), "r"(b1));
}

__device__ __forceinline__ int tiled_nk(int n, int k) {   // Q/K/W layout
    return ((n >> 3) * 16 + (k >> 3)) * 64 + (n & 7) * 8 + 2 * (k & 3) + ((k & 4) >> 2);
}
__device__ __forceinline__ int tiled_v(int m, int d) {    // V layout
    return ((m >> 3) * 16 + (d >> 3)) * 64 + (d & 7) * 8 + 2 * (m & 3) + ((m & 4) >> 2);
}

__device__ __forceinline__ uint32_t smem_u32(const void* p) {
    return (uint32_t)__cvta_generic_to_shared(p);
}
__device__ __forceinline__ void cp16(uint32_t dst, const void* src) {
    asm volatile("cp.async.cg.shared.global [%0], [%1], 16;" :: "r"(dst), "l"(src));
}
#define CP_COMMIT() asm volatile("cp.async.commit_group;")
#define CP_WAIT0()  asm volatile("cp.async.wait_group 0;")
#define CP_WAIT1()  asm volatile("cp.async.wait_group 1;")

// ---------------------------------------------------------------------------
// Kernel B (first -> profile slot): KV = tf32( x2 @ W2^T + b2 )
// [R15 committed win: W2 resident tiled, 8 windows/CTA, cp.async x2 staging]
// ---------------------------------------------------------------------------
#define KV_GW 8
#define KV_SMEM_FLOATS (32768 + 2 * 8448)

__global__ void __launch_bounds__(512, 1) kv_kernel(
    const float* __restrict__ x2, const float* __restrict__ w2,
    const float* __restrict__ bias2)
{
    extern __shared__ float sm[];
    float* w_s = sm;

    const int t = threadIdx.x;
    const int lane = t & 31, wid = t >> 5;
    const int m_base = (wid & 3) * 16;
    const int n_base = (wid >> 2) * 64;
    const int r0 = lane >> 2, cth = lane & 3;
    const int base = blockIdx.x * KV_GW;

    for (int idx = t; idx < 8192; idx += 512) {
        const int j = idx >> 5, k4 = (idx & 31) * 4;
        const float4 w = *(const float4*)(w2 + j * DIM + k4);
        w_s[tiled_nk(j, k4 + 0)] = to_tf32(w.x);
        w_s[tiled_nk(j, k4 + 1)] = to_tf32(w.y);
        w_s[tiled_nk(j, k4 + 2)] = to_tf32(w.z);
        w_s[tiled_nk(j, k4 + 3)] = to_tf32(w.w);
    }

    {
        const float* xb = x2 + (size_t)base * 8192;
        float* a0 = sm + 32768;
#pragma unroll
        for (int i = 0; i < 4; i++) {
            const int idx = t + i * 512;
            const int m = idx >> 5, k4 = (idx & 31) * 4;
            cp16(smem_u32(a0 + m * 132 + k4), xb + m * DIM + k4);
        }
        CP_COMMIT();
    }

    for (int g = 0; g < KV_GW; g++) {
        const int b2 = base + g;

        __syncthreads();
        if (g < KV_GW - 1) {
            const float* xn = x2 + (size_t)(b2 + 1) * 8192;
            float* an = sm + 32768 + ((g + 1) & 1) * 8448;
#pragma unroll
            for (int i = 0; i < 4; i++) {
                const int idx = t + i * 512;
                const int m = idx >> 5, k4 = (idx & 31) * 4;
                cp16(smem_u32(an + m * 132 + k4), xn + m * DIM + k4);
            }
            CP_COMMIT();
            CP_WAIT1();
        } else {
            CP_WAIT0();
        }
        __syncthreads();

        const float* a_s = sm + 32768 + (g & 1) * 8448;

        float c[8][4];
#pragma unroll
        for (int nt = 0; nt < 8; nt++)
#pragma unroll
            for (int j = 0; j < 4; j++) c[nt][j] = 0.f;

#pragma unroll
        for (int kc = 0; kc < 4; kc++) {
#pragma unroll
            for (int ks = 0; ks < 4; ks++) {
                const int col = kc * 32 + ks * 8 + cth;
                const uint32_t a0 = __float_as_uint(a_s[(m_base + r0) * 132 + col]);
                const uint32_t a1 = __float_as_uint(a_s[(m_base + r0 + 8) * 132 + col]);
                const uint32_t a2 = __float_as_uint(a_s[(m_base + r0) * 132 + col + 4]);
                const uint32_t a3 = __float_as_uint(a_s[(m_base + r0 + 8) * 132 + col + 4]);
                const int ktile = kc * 4 + ks;
#pragma unroll
                for (int nt = 0; nt < 8; nt++) {
                    const int tile = ((n_base >> 3) + nt) * 16 + ktile;
                    const float2 bp = *(const float2*)&w_s[tile * 64 + r0 * 8 + 2 * cth];
                    mma_tf32(c[nt], a0, a1, a2, a3,
                             __float_as_uint(bp.x), __float_as_uint(bp.y));
                }
            }
        }

        float* dst = g_KV + (size_t)b2 * 16384;
        const int row0 = m_base + r0;
#pragma unroll
        for (int nt = 0; nt < 8; nt++) {
            const int col0 = n_base + nt * 8 + 2 * cth;
            const float2 bv = *(const float2*)(bias2 + col0);
            const float v00 = to_tf32(c[nt][0] + bv.x);
            const float v01 = to_tf32(c[nt][1] + bv.y);
            const float v10 = to_tf32(c[nt][2] + bv.x);
            const float v11 = to_tf32(c[nt][3] + bv.y);
            if (col0 < DIM) {
                dst[tiled_nk(row0,     col0    )] = v00;
                dst[tiled_nk(row0,     col0 + 1)] = v01;
                dst[tiled_nk(row0 + 8, col0    )] = v10;
                dst[tiled_nk(row0 + 8, col0 + 1)] = v11;
            } else {
                const int d0 = col0 - DIM;
                dst[8192 + tiled_v(row0,     d0    )] = v00;
                dst[8192 + tiled_v(row0,     d0 + 1)] = v01;
                dst[8192 + tiled_v(row0 + 8, d0    )] = v10;
                dst[8192 + tiled_v(row0 + 8, d0 + 1)] = v11;
            }
        }
    }
}

// ---------------------------------------------------------------------------
// Kernel A: Q = tf32( scale * (x1 @ W1^T + b1) )  [unchanged]
// ---------------------------------------------------------------------------
#define QK_SMEM_FLOATS (8448 + 4608)

__global__ void __launch_bounds__(256) q_kernel(
    const float* __restrict__ x1, const float* __restrict__ w1,
    const float* __restrict__ bias1)
{
    extern __shared__ float sm[];
    float* a_s = sm;
    float* w_s = sm + 8448;

    const int t = threadIdx.x, b = blockIdx.x;
    const int lane = t & 31, wid = t >> 5;
    const int m_base = (wid & 3) * 16;
    const int n_base = (wid >> 2) * 64;
    const int r0 = lane >> 2, cth = lane & 3;

    const float* xb = x1 + (size_t)b * (NTOK * DIM);
    for (int idx = t; idx < NTOK * DIM; idx += 256) {
        int m = idx >> 7, k = idx & 127;
        a_s[m * 132 + k] = to_tf32(xb[idx]);
    }

    float c[8][4];
#pragma unroll
    for (int nt = 0; nt < 8; nt++)
#pragma unroll
        for (int j = 0; j < 4; j++) c[nt][j] = 0.f;

    for (int kc = 0; kc < 4; kc++) {
        __syncthreads();
        for (int idx = t; idx < 4096; idx += 256) {
            int j = idx >> 5, kk = idx & 31;
            w_s[j * 36 + kk] = to_tf32(w1[j * DIM + kc * 32 + kk]);
        }
        __syncthreads();
#pragma unroll
        for (int ks = 0; ks < 4; ks++) {
            const int col = kc * 32 + ks * 8 + cth;
            const uint32_t a0 = __float_as_uint(a_s[(m_base + r0) * 132 + col]);
            const uint32_t a1 = __float_as_uint(a_s[(m_base + r0 + 8) * 132 + col]);
            const uint32_t a2 = __float_as_uint(a_s[(m_base + r0) * 132 + col + 4]);
            const uint32_t a3 = __float_as_uint(a_s[(m_base + r0 + 8) * 132 + col + 4]);
#pragma unroll
            for (int nt = 0; nt < 8; nt++) {
                const int j = n_base + nt * 8 + r0;
                const uint32_t b0 = __float_as_uint(w_s[j * 36 + ks * 8 + cth]);
                const uint32_t b1 = __float_as_uint(w_s[j * 36 + ks * 8 + 4 + cth]);
                mma_tf32(c[nt], a0, a1, a2, a3, b0, b1);
            }
        }
    }

    float* qb = g_Q + (size_t)b * 8192;
    const int row0 = m_base + r0;
#pragma unroll
    for (int nt = 0; nt < 8; nt++) {
        const int col0 = n_base + nt * 8 + 2 * cth;
        const float2 bv = *(const float2*)(bias1 + col0);
        qb[tiled_nk(row0,     col0    )] = to_tf32((c[nt][0] + bv.x) * QSCALE);
        qb[tiled_nk(row0,     col0 + 1)] = to_tf32((c[nt][1] + bv.y) * QSCALE);
        qb[tiled_nk(row0 + 8, col0    )] = to_tf32((c[nt][2] + bv.x) * QSCALE);
        qb[tiled_nk(row0 + 8, col0 + 1)] = to_tf32((c[nt][3] + bv.y) * QSCALE);
    }
}

// ---------------------------------------------------------------------------
// Kernel C v4: 256 threads (8 warps), 2 CTAs/SM. Each warp runs TWO
// (h, slab) jobs per window. Single KV stage buffer (the co-resident CTA
// hides stage latency). Same per-job math/order as R15 -> identical bits.
// smem: stage [0:16384) | rel u16 [16384:18432) | tab [18432:19332)
// tail: o_s [0:8192) | pw_s [8192:24576)  (overlaps dead rel/tab)
// ---------------------------------------------------------------------------
#define ATTN_SMEM_FLOATS 24576   // 98304 B

__global__ void __launch_bounds__(256, 2) attn_kernel(
    const float* __restrict__ pw, const float* __restrict__ pb,
    const float* __restrict__ rpb, const int* __restrict__ rel,
    float* __restrict__ out)
{
    extern __shared__ float sm[];
    uint16_t* rel_s = (uint16_t*)(sm + 16384);
    float*    tab_s = sm + 18432;

    const int t    = threadIdx.x;
    const int bdst = blockIdx.x;
    const int lane = t & 31, wid = t >> 5;     // wid 0..7
    const int r0 = lane >> 2, cth = lane & 3;
    const int ldoff = r0 * 8 + 2 * cth;

    for (int idx = t; idx < NTOK * NTOK; idx += 256)
        rel_s[idx] = (uint16_t)rel[idx];
    for (int idx = t; idx < 225 * 4; idx += 256)
        tab_s[idx] = rpb[idx];

    float oacc[2][4][4];
#pragma unroll
    for (int jj = 0; jj < 2; jj++)
#pragma unroll
        for (int nt = 0; nt < 4; nt++)
#pragma unroll
            for (int j = 0; j < 4; j++) oacc[jj][nt][j] = 0.f;

    for (int r = 0; r < 4; r++) {
        const int b2 = bdst * 4 + r;

        __syncthreads();   // previous window's readers done (r=0: orders rel/tab)
        {
            const float4* kvg = (const float4*)(g_KV + (size_t)b2 * 16384);
#pragma unroll
            for (int i = 0; i < 16; i++) {
                const int idx = t + i * 256;      // 0..4095
                cp16(smem_u32(sm + idx * 4), kvg + idx);
            }
            CP_COMMIT();
            CP_WAIT0();
        }
        __syncthreads();   // K|V visible

        float* k_s = sm;
        float* v_s = sm + 8192;
        const int qb = b2 & (B1N - 1);
        const float* qg = g_Q + (size_t)qb * 8192;

#pragma unroll
        for (int jj = 0; jj < 2; jj++) {
            const int job = wid + jj * 8;          // 0..15
            const int h   = job >> 2;
            const int R0  = (job & 3) * 16;
            const int n_lo = R0 + r0, n_hi = n_lo + 8;

            // Q A-frags direct from L2 (tiled)
            float2 qalo[4], qahi[4];
#pragma unroll
            for (int ks = 0; ks < 4; ks++) {
                const int kt = h * 4 + ks;
                qalo[ks] = *(const float2*)&qg[(((R0 >> 3)    ) * 16 + kt) * 64 + ldoff];
                qahi[ks] = *(const float2*)&qg[(((R0 >> 3) + 1) * 16 + kt) * 64 + ldoff];
            }

            // ---- S = Q K^T ----
            float c[8][4];
#pragma unroll
            for (int nt = 0; nt < 8; nt++)
#pragma unroll
                for (int j = 0; j < 4; j++) c[nt][j] = 0.f;

#pragma unroll
            for (int ks = 0; ks < 4; ks++) {
                const int kt = h * 4 + ks;
                const uint32_t a0 = __float_as_uint(qalo[ks].x);
                const uint32_t a1 = __float_as_uint(qahi[ks].x);
                const uint32_t a2 = __float_as_uint(qalo[ks].y);
                const uint32_t a3 = __float_as_uint(qahi[ks].y);
#pragma unroll
                for (int nt = 0; nt < 8; nt++) {
                    const float2 bp = *(const float2*)&k_s[(nt * 16 + kt) * 64 + ldoff];
                    mma_tf32(c[nt], a0, a1, a2, a3,
                             __float_as_uint(bp.x), __float_as_uint(bp.y));
                }
            }

            // ---- + relative position bias ----
#pragma unroll
            for (int nt = 0; nt < 8; nt++) {
                const int m = nt * 8 + 2 * cth;
                const uint32_t rlo = *(const uint32_t*)&rel_s[n_lo * 64 + m];
                const uint32_t rhi = *(const uint32_t*)&rel_s[n_hi * 64 + m];
                c[nt][0] += tab_s[(rlo & 0xffff) * 4 + h];
                c[nt][1] += tab_s[(rlo >> 16) * 4 + h];
                c[nt][2] += tab_s[(rhi & 0xffff) * 4 + h];
                c[nt][3] += tab_s[(rhi >> 16) * 4 + h];
            }

            // ---- softmax ----
            float mx0 = -1e30f, mx1 = -1e30f;
#pragma unroll
            for (int nt = 0; nt < 8; nt++) {
                mx0 = fmaxf(mx0, fmaxf(c[nt][0], c[nt][1]));
                mx1 = fmaxf(mx1, fmaxf(c[nt][2], c[nt][3]));
            }
            mx0 = fmaxf(mx0, __shfl_xor_sync(0xffffffffu, mx0, 1));
            mx0 = fmaxf(mx0, __shfl_xor_sync(0xffffffffu, mx0, 2));
            mx1 = fmaxf(mx1, __shfl_xor_sync(0xffffffffu, mx1, 1));
            mx1 = fmaxf(mx1, __shfl_xor_sync(0xffffffffu, mx1, 2));

            float s0 = 0.f, s1 = 0.f;
#pragma unroll
            for (int nt = 0; nt < 8; nt++) {
                c[nt][0] = __expf(c[nt][0] - mx0); s0 += c[nt][0];
                c[nt][1] = __expf(c[nt][1] - mx0); s0 += c[nt][1];
                c[nt][2] = __expf(c[nt][2] - mx1); s1 += c[nt][2];
                c[nt][3] = __expf(c[nt][3] - mx1); s1 += c[nt][3];
            }
            s0 += __shfl_xor_sync(0xffffffffu, s0, 1);
            s0 += __shfl_xor_sync(0xffffffffu, s0, 2);
            s1 += __shfl_xor_sync(0xffffffffu, s1, 1);
            s1 += __shfl_xor_sync(0xffffffffu, s1, 2);
            const float inv0 = 1.f / s0, inv1 = 1.f / s1;
#pragma unroll
            for (int nt = 0; nt < 8; nt++) {
                c[nt][0] *= inv0; c[nt][1] *= inv0;
                c[nt][2] *= inv1; c[nt][3] *= inv1;
            }

            // ---- write attn probs ----
            float* ao = out + (size_t)X_ELEMS + (size_t)b2 * 16384 + h * 4096;
#pragma unroll
            for (int nt = 0; nt < 8; nt++) {
                const int m = nt * 8 + 2 * cth;
                *(float2*)&ao[n_lo * 64 + m] = make_float2(c[nt][0], c[nt][1]);
                *(float2*)&ao[n_hi * 64 + m] = make_float2(c[nt][2], c[nt][3]);
            }

            // ---- round P, C-frag -> A-frag shuffles, PV mma ----
#pragma unroll
            for (int nt = 0; nt < 8; nt++)
#pragma unroll
                for (int j = 0; j < 4; j++) c[nt][j] = to_tf32(c[nt][j]);

            const int src0 = (lane & 28) + (cth >> 1);
            const int src1 = src0 + 2;
            const bool odd = (cth & 1);
#pragma unroll
            for (int ks = 0; ks < 8; ks++) {
                const float e0 = __shfl_sync(0xffffffffu, c[ks][0], src0);
                const float o0 = __shfl_sync(0xffffffffu, c[ks][1], src0);
                const float e2 = __shfl_sync(0xffffffffu, c[ks][0], src1);
                const float o2 = __shfl_sync(0xffffffffu, c[ks][1], src1);
                const float e1 = __shfl_sync(0xffffffffu, c[ks][2], src0);
                const float o1 = __shfl_sync(0xffffffffu, c[ks][3], src0);
                const float e3 = __shfl_sync(0xffffffffu, c[ks][2], src1);
                const float o3 = __shfl_sync(0xffffffffu, c[ks][3], src1);
                const uint32_t pa0 = __float_as_uint(odd ? o0 : e0);
                const uint32_t pa1 = __float_as_uint(odd ? o1 : e1);
                const uint32_t pa2 = __float_as_uint(odd ? o2 : e2);
                const uint32_t pa3 = __float_as_uint(odd ? o3 : e3);
#pragma unroll
                for (int nt = 0; nt < 4; nt++) {
                    const float2 bp = *(const float2*)&v_s[(ks * 16 + h * 4 + nt) * 64 + ldoff];
                    mma_tf32(oacc[jj][nt], pa0, pa1, pa2, pa3,
                             __float_as_uint(bp.x), __float_as_uint(bp.y));
                }
            }
        } // jj
    } // r

    // ---- tail: O tiled -> o_s, pw tiled -> pw_s, proj via tf32 mma ----
    __syncthreads();
    float* o_s  = sm;            // 8192 floats
    float* pw_s = sm + 8192;     // 16384 floats (overlaps dead rel/tab)

#pragma unroll
    for (int jj = 0; jj < 2; jj++) {
        const int job = wid + jj * 8;
        const int h   = job >> 2;
        const int R0  = (job & 3) * 16;
        const int n_lo = R0 + r0, n_hi = n_lo + 8;
#pragma unroll
        for (int nt = 0; nt < 4; nt++) {
            const int d0 = h * 32 + nt * 8 + 2 * cth;
            o_s[tiled_nk(n_lo, d0    )] = to_tf32(oacc[jj][nt][0]);
            o_s[tiled_nk(n_lo, d0 + 1)] = to_tf32(oacc[jj][nt][1]);
            o_s[tiled_nk(n_hi, d0    )] = to_tf32(oacc[jj][nt][2]);
            o_s[tiled_nk(n_hi, d0 + 1)] = to_tf32(oacc[jj][nt][3]);
        }
    }
    for (int idx = t; idx < 4096; idx += 256) {
        const int j = idx >> 5, k4 = (idx & 31) * 4;
        const float4 w = *(const float4*)(pw + j * DIM + k4);
        pw_s[tiled_nk(j, k4 + 0)] = to_tf32(w.x);
        pw_s[tiled_nk(j, k4 + 1)] = to_tf32(w.y);
        pw_s[tiled_nk(j, k4 + 2)] = to_tf32(w.z);
        pw_s[tiled_nk(j, k4 + 3)] = to_tf32(w.w);
    }
    __syncthreads();

    float* xo = out + (size_t)bdst * (NTOK * DIM);
#pragma unroll
    for (int jj = 0; jj < 2; jj++) {
        const int pjob  = wid + jj * 8;
        const int slab  = (pjob & 3) * 16;
        const int jbase = (pjob >> 2) * 32;
        float pc[4][4];
#pragma unroll
        for (int nt = 0; nt < 4; nt++)
#pragma unroll
            for (int j = 0; j < 4; j++) pc[nt][j] = 0.f;

#pragma unroll
        for (int kt = 0; kt < 16; kt++) {
            const float2 alo = *(const float2*)&o_s[(((slab >> 3)    ) * 16 + kt) * 64 + ldoff];
            const float2 ahi = *(const float2*)&o_s[(((slab >> 3) + 1) * 16 + kt) * 64 + ldoff];
            const uint32_t a0 = __float_as_uint(alo.x);
            const uint32_t a1 = __float_as_uint(ahi.x);
            const uint32_t a2 = __float_as_uint(alo.y);
            const uint32_t a3 = __float_as_uint(ahi.y);
#pragma unroll
            for (int nt = 0; nt < 4; nt++) {
                const float2 bp = *(const float2*)&pw_s[(((jbase >> 3) + nt) * 16 + kt) * 64 + ldoff];
                mma_tf32(pc[nt], a0, a1, a2, a3,
                         __float_as_uint(bp.x), __float_as_uint(bp.y));
            }
        }

        const int prow = slab + r0;
#pragma unroll
        for (int nt = 0; nt < 4; nt++) {
            const int col0 = jbase + nt * 8 + 2 * cth;
            const float2 bv = *(const float2*)(pb + col0);
            *(float2*)&xo[prow * DIM + col0] =
                make_float2(pc[nt][0] + bv.x, pc[nt][1] + bv.y);
            *(float2*)&xo[(prow + 8) * DIM + col0] =
                make_float2(pc[nt][2] + bv.x, pc[nt][3] + bv.y);
        }
    }
}

// ---------------------------------------------------------------------------
extern "C" void kernel_launch(void* const* d_in, const int* in_sizes, int n_in,
                              void* d_out, int out_size)
{
    const float* x1     = (const float*)d_in[0];
    const float* x2     = (const float*)d_in[1];
    const float* qkv1_w = (const float*)d_in[2];
    const float* qkv1_b = (const float*)d_in[3];
    const float* qkv2_w = (const float*)d_in[4];
    const float* qkv2_b = (const float*)d_in[5];
    const float* proj_w = (const float*)d_in[6];
    const float* proj_b = (const float*)d_in[7];
    const float* rpb    = (const float*)d_in[8];
    const int*   rel    = (const int*)d_in[9];
    float* out = (float*)d_out;

    static bool attr_set = false;
    if (!attr_set) {
        cudaFuncSetAttribute(q_kernel,
                             cudaFuncAttributeMaxDynamicSharedMemorySize,
                             QK_SMEM_FLOATS * sizeof(float));
        cudaFuncSetAttribute(kv_kernel,
                             cudaFuncAttributeMaxDynamicSharedMemorySize,
                             KV_SMEM_FLOATS * sizeof(float));
        cudaFuncSetAttribute(attn_kernel,
                             cudaFuncAttributeMaxDynamicSharedMemorySize,
                             ATTN_SMEM_FLOATS * sizeof(float));
        attr_set = true;
    }

    kv_kernel<<<B2N / KV_GW, 512, KV_SMEM_FLOATS * sizeof(float)>>>(x2, qkv2_w, qkv2_b);
    q_kernel<<<B1N, 256, QK_SMEM_FLOATS * sizeof(float)>>>(x1, qkv1_w, qkv1_b);
    attn_kernel<<<B1N, 256, ATTN_SMEM_FLOATS * sizeof(float)>>>(
        proj_w, proj_b, rpb, rel, out);
}